// round 6
// baseline (speedup 1.0000x reference)
#include <cuda_runtime.h>
#include <math.h>

#define T 256
#define H 1024
#define E 256
#define I_DIM 256
#define SEG_CAP 16
#define NSEG_MAX 416
#define NSLOT (2048 + 256)
#define RPAD 18                       // padded row stride (u64) for dup buffers

typedef unsigned long long u64;

// ---- static scratch ----
__device__ int   d_cnt[E];
__device__ int   d_off[E];
__device__ int   d_tokbuf[E * T];
__device__ float d_wbuf[E * T];
__device__ int   d_nseg;
__device__ int   d_seg_e[NSEG_MAX];
__device__ int   d_seg_nt[NSEG_MAX];
__device__ int   d_seg_slot0[NSEG_MAX];
__device__ int   d_seg_tok[NSEG_MAX * SEG_CAP];
__device__ float d_seg_wt[NSEG_MAX * SEG_CAP];
__device__ __align__(16) float d_ps[NSLOT * I_DIM];

// ---- f32x2 helpers ----
__device__ __forceinline__ u64 dup2f(float v) {
    u64 r; asm("mov.b64 %0,{%1,%1};" : "=l"(r) : "f"(v)); return r;
}
__device__ __forceinline__ u64 fma2(u64 a, u64 b, u64 c) {
    u64 d; asm("fma.rn.f32x2 %0,%1,%2,%3;" : "=l"(d) : "l"(a), "l"(b), "l"(c)); return d;
}
__device__ __forceinline__ float2 unpk(u64 a) {
    float2 f; asm("mov.b64 {%0,%1},%2;" : "=f"(f.x), "=f"(f.y) : "l"(a)); return f;
}

// ============================================================
// 0) init: zero output + per-expert counters
// ============================================================
__global__ void k_init(float4* y)
{
    y[blockIdx.x * 256 + threadIdx.x] = make_float4(0.f, 0.f, 0.f, 0.f);
    if (blockIdx.x == 0) d_cnt[threadIdx.x] = 0;
}

// ============================================================
// 1) gate logits + noaux_tc routing. 4 tokens per block.
// ============================================================
__global__ void k_route(const float* __restrict__ x,
                        const float* __restrict__ gw,
                        const float* __restrict__ ebias)
{
    __shared__ float xs[4][H];
    __shared__ float s_scores[4][E];
    __shared__ float s_sc[4][E];

    int tid  = threadIdx.x;
    int lane = tid & 31;
    int wid  = tid >> 5;
    int t0   = blockIdx.x * 4;

    for (int t = 0; t < 4; t++)
        for (int k = tid; k < H; k += 256)
            xs[t][k] = x[(t0 + t) * H + k];
    __syncthreads();

    for (int eo = 0; eo < 32; eo++) {
        int e = wid * 32 + eo;
        const float* wr = gw + e * H;
        float a0 = 0.f, a1 = 0.f, a2 = 0.f, a3 = 0.f;
        #pragma unroll 4
        for (int k = 0; k < 32; k++) {
            float wv = wr[k * 32 + lane];
            a0 += wv * xs[0][k * 32 + lane];
            a1 += wv * xs[1][k * 32 + lane];
            a2 += wv * xs[2][k * 32 + lane];
            a3 += wv * xs[3][k * 32 + lane];
        }
        for (int off = 16; off; off >>= 1) {
            a0 += __shfl_xor_sync(~0u, a0, off);
            a1 += __shfl_xor_sync(~0u, a1, off);
            a2 += __shfl_xor_sync(~0u, a2, off);
            a3 += __shfl_xor_sync(~0u, a3, off);
        }
        if (lane == 0) {
            float b = ebias[e];
            float s;
            s = 1.f / (1.f + expf(-a0)); s_scores[0][e] = s; s_sc[0][e] = s + b;
            s = 1.f / (1.f + expf(-a1)); s_scores[1][e] = s; s_sc[1][e] = s + b;
            s = 1.f / (1.f + expf(-a2)); s_scores[2][e] = s; s_sc[2][e] = s + b;
            s = 1.f / (1.f + expf(-a3)); s_scores[3][e] = s; s_sc[3][e] = s + b;
        }
    }
    __syncthreads();

    if (wid < 4) {
        int t     = wid;
        int tglob = t0 + t;

        float gs[8];
        #pragma unroll
        for (int g = 0; g < 8; g++) {
            float v  = s_sc[t][g * 32 + lane];
            float m1 = v; int i1 = lane;
            for (int off = 16; off; off >>= 1) {
                float ov = __shfl_xor_sync(~0u, m1, off);
                int   oi = __shfl_xor_sync(~0u, i1, off);
                if (ov > m1 || (ov == m1 && oi < i1)) { m1 = ov; i1 = oi; }
            }
            float v2 = (lane == i1) ? -INFINITY : v;
            for (int off = 16; off; off >>= 1)
                v2 = fmaxf(v2, __shfl_xor_sync(~0u, v2, off));
            gs[g] = m1 + v2;
        }

        unsigned gmask = 0;
        #pragma unroll
        for (int r = 0; r < 4; r++) {
            float bv = -INFINITY; int bg = 0;
            #pragma unroll
            for (int g = 0; g < 8; g++)
                if (!((gmask >> g) & 1) && gs[g] > bv) { bv = gs[g]; bg = g; }
            gmask |= 1u << bg;
        }

        float mv[8];
        #pragma unroll
        for (int j = 0; j < 8; j++)
            mv[j] = ((gmask >> j) & 1) ? s_sc[t][lane + 32 * j] : -INFINITY;

        int sel[8];
        #pragma unroll
        for (int r = 0; r < 8; r++) {
            float bv = -INFINITY; int be = 1 << 30;
            #pragma unroll
            for (int j = 0; j < 8; j++) {
                int e = lane + 32 * j;
                if (mv[j] > bv || (mv[j] == bv && e < be)) { bv = mv[j]; be = e; }
            }
            for (int off = 16; off; off >>= 1) {
                float ov = __shfl_xor_sync(~0u, bv, off);
                int   oe = __shfl_xor_sync(~0u, be, off);
                if (ov > bv || (ov == bv && oe < be)) { bv = ov; be = oe; }
            }
            sel[r] = be;
            if ((be & 31) == lane) mv[be >> 5] = -INFINITY;
        }

        float myv = (lane < 8) ? s_scores[t][sel[lane]] : 0.f;
        float sum = myv;
        for (int off = 16; off; off >>= 1)
            sum += __shfl_xor_sync(~0u, sum, off);
        if (lane < 8) {
            float wt = myv / (sum + 1e-20f) * 2.5f;
            int e = sel[lane];
            int pos = atomicAdd(&d_cnt[e], 1);
            d_tokbuf[e * T + pos] = tglob;
            d_wbuf[e * T + pos]  = wt;
        }
    }
}

// ============================================================
// 2) scan: per-expert offsets + segment list (+16 shared segs)
// ============================================================
__global__ void k_scan()
{
    __shared__ int s1[E], s2[E];
    int e = threadIdx.x;
    int n = d_cnt[e];

    s1[e] = n; __syncthreads();
    for (int d = 1; d < E; d <<= 1) {
        int v = (e >= d) ? s1[e - d] : 0;
        __syncthreads();
        s1[e] += v;
        __syncthreads();
    }
    int off = s1[e] - n;
    d_off[e] = off;

    int nseg = (n + SEG_CAP - 1) / SEG_CAP;
    s2[e] = nseg; __syncthreads();
    for (int d = 1; d < E; d <<= 1) {
        int v = (e >= d) ? s2[e - d] : 0;
        __syncthreads();
        s2[e] += v;
        __syncthreads();
    }
    int segbase = 16 + (s2[e] - nseg);
    if (e == E - 1) d_nseg = 16 + s2[E - 1];

    for (int si = 0; si < nseg; si++) {
        int sidx = segbase + si;
        int st   = si * SEG_CAP;
        int cnt  = min(SEG_CAP, n - st);
        d_seg_e[sidx]     = e;
        d_seg_nt[sidx]    = cnt;
        d_seg_slot0[sidx] = off + st;
        for (int j = 0; j < cnt; j++) {
            d_seg_tok[sidx * SEG_CAP + j] = d_tokbuf[e * T + st + j];
            d_seg_wt[sidx * SEG_CAP + j]  = d_wbuf[e * T + st + j];
        }
    }

    if (e < 16) {
        d_seg_e[e]     = E;
        d_seg_nt[e]    = SEG_CAP;
        d_seg_slot0[e] = 2048 + e * SEG_CAP;
        for (int j = 0; j < SEG_CAP; j++) {
            d_seg_tok[e * SEG_CAP + j] = e * SEG_CAP + j;
            d_seg_wt[e * SEG_CAP + j]  = 1.0f;
        }
    }
}

// FMA step: one weight row (ulonglong2 = 4 cols) x 8 tokens
#define UP_FMA(W, ROW)                                              \
    {                                                               \
        const u64* _r = (ROW);                                      \
        _Pragma("unroll")                                           \
        for (int p = 0; p < 4; p++) {                               \
            ulonglong2 xp = *(const ulonglong2*)(_r + 2 * p);       \
            a0[2*p]   = fma2(xp.x, (W).x, a0[2*p]);                 \
            a1[2*p]   = fma2(xp.x, (W).y, a1[2*p]);                 \
            a0[2*p+1] = fma2(xp.y, (W).x, a0[2*p+1]);               \
            a1[2*p+1] = fma2(xp.y, (W).y, a1[2*p+1]);               \
        }                                                           \
    }

// ============================================================
// 3) up/gate. 1 block/seg. thread = (g:64 x 4cols, m:gate/up,
//    th: token-half). 16 u64 accs/thread. Full-k, no reduction.
// ============================================================
__global__ void __launch_bounds__(256, 3) k_up(
    const float* __restrict__ x,
    const float* __restrict__ w_gate, const float* __restrict__ w_up,
    const float* __restrict__ sw_gate, const float* __restrict__ sw_up)
{
    extern __shared__ u64 sm[];      // 256 rows x RPAD u64 = 36 KB
    __shared__ int s_tok[SEG_CAP];
    int seg = blockIdx.x;
    if (seg >= d_nseg) return;
    int e     = d_seg_e[seg];
    int nt    = d_seg_nt[seg];
    int slot0 = d_seg_slot0[seg];
    int tid = threadIdx.x;
    int g  = tid & 63;
    int m  = (tid >> 6) & 1;
    int th = tid >> 7;

    if (tid < SEG_CAP) s_tok[tid] = d_seg_tok[seg * SEG_CAP + min(tid, nt - 1)];

    const float* wf;
    if (e < E) wf = m ? (w_up + (size_t)e * H * I_DIM) : (w_gate + (size_t)e * H * I_DIM);
    else       wf = m ? sw_up : sw_gate;
    const ulonglong2* wmat = (const ulonglong2*)wf;

    u64 a0[8], a1[8];
    #pragma unroll
    for (int j = 0; j < 8; j++) { a0[j] = 0ull; a1[j] = 0ull; }

    for (int c = 0; c < 4; c++) {        // 4 chunks of 256 h
        __syncthreads();
        // stage dup-x: row hh (0..255), token-contiguous u64 cols 0..15
        for (int idx = tid; idx < 16 * 128; idx += 256) {
            int j  = idx >> 7;           // token
            int hp = idx & 127;          // h float2 index
            float2 v = *(const float2*)(x + (size_t)s_tok[j] * H + c * 256 + hp * 2);
            int col = (j >> 1) * 2 + (j & 1);
            sm[(size_t)(2 * hp)     * RPAD + col] = dup2f(v.x);
            sm[(size_t)(2 * hp + 1) * RPAD + col] = dup2f(v.y);
        }
        __syncthreads();

        const ulonglong2* wp = wmat + (size_t)(c * 256) * 64 + g;
        const u64* xb = sm + th * 8;
        #pragma unroll 2
        for (int k0 = 0; k0 < 256; k0 += 4) {
            ulonglong2 w0 = wp[(size_t)(k0 + 0) * 64];
            ulonglong2 w1 = wp[(size_t)(k0 + 1) * 64];
            ulonglong2 w2 = wp[(size_t)(k0 + 2) * 64];
            ulonglong2 w3 = wp[(size_t)(k0 + 3) * 64];
            UP_FMA(w0, xb + (size_t)(k0 + 0) * RPAD);
            UP_FMA(w1, xb + (size_t)(k0 + 1) * RPAD);
            UP_FMA(w2, xb + (size_t)(k0 + 2) * RPAD);
            UP_FMA(w3, xb + (size_t)(k0 + 3) * RPAD);
        }
    }

    // epilogue: gate threads (m=0) publish partials; up threads combine
    __syncthreads();
    if (m == 0) {
        #pragma unroll
        for (int j = 0; j < 8; j++) {
            ulonglong2 v; v.x = a0[j]; v.y = a1[j];
            *(ulonglong2*)(sm + (size_t)(th * 8 + j) * 128 + 2 * g) = v;
        }
    }
    __syncthreads();
    if (m == 1) {
        float* psout = d_ps + (size_t)slot0 * I_DIM;
        #pragma unroll
        for (int j = 0; j < 8; j++) {
            int t = th * 8 + j;
            if (t < nt) {
                ulonglong2 gg = *(const ulonglong2*)(sm + (size_t)t * 128 + 2 * g);
                float2 g0 = unpk(gg.x), g1 = unpk(gg.y);
                float2 u0 = unpk(a0[j]), u1 = unpk(a1[j]);
                float4 r;
                r.x = g0.x / (1.f + expf(-g0.x)) * u0.x;
                r.y = g0.y / (1.f + expf(-g0.y)) * u0.y;
                r.z = g1.x / (1.f + expf(-g1.x)) * u1.x;
                r.w = g1.y / (1.f + expf(-g1.y)) * u1.y;
                *(float4*)(psout + (size_t)t * I_DIM + 4 * g) = r;
            }
        }
    }
}

// ============================================================
// 4) down. grid (2, seg). thread = (g:128 x 4cols of 512-half,
//    th: token-half). 16 u64 accs. REDG epilogue.
// ============================================================
__global__ void __launch_bounds__(256, 3) k_down(
    const float* __restrict__ w_down, const float* __restrict__ sw_down,
    float* __restrict__ y)
{
    extern __shared__ u64 sm[];      // 256 rows x RPAD u64 = 36 KB
    __shared__ int   s_tok[SEG_CAP];
    __shared__ float s_wt[SEG_CAP];
    int seg = blockIdx.y;
    if (seg >= d_nseg) return;
    int e     = d_seg_e[seg];
    int nt    = d_seg_nt[seg];
    int slot0 = d_seg_slot0[seg];
    int hc    = blockIdx.x;
    int tid = threadIdx.x;
    int g  = tid & 127;
    int th = tid >> 7;

    if (tid < SEG_CAP) {
        s_tok[tid] = d_seg_tok[seg * SEG_CAP + min(tid, nt - 1)];
        s_wt[tid]  = (tid < nt) ? d_seg_wt[seg * SEG_CAP + tid] : 0.f;
    }
    const ulonglong2* wd = (const ulonglong2*)((e < E) ? (w_down + (size_t)e * I_DIM * H) : sw_down);
    const float* psin = d_ps + (size_t)slot0 * I_DIM;
    __syncthreads();

    // stage dup-ps: row i (0..255), token-contiguous
    for (int idx = tid; idx < 16 * 128; idx += 256) {
        int j  = idx >> 7;
        int ip = idx & 127;
        float2 v = *(const float2*)(psin + (size_t)j * I_DIM + ip * 2);
        int col = (j >> 1) * 2 + (j & 1);
        sm[(size_t)(2 * ip)     * RPAD + col] = dup2f(v.x);
        sm[(size_t)(2 * ip + 1) * RPAD + col] = dup2f(v.y);
    }
    __syncthreads();

    u64 a0[8], a1[8];
    #pragma unroll
    for (int j = 0; j < 8; j++) { a0[j] = 0ull; a1[j] = 0ull; }

    const ulonglong2* wp = wd + (size_t)hc * 128 + g;
    const u64* xb = sm + th * 8;
    #pragma unroll 2
    for (int i0 = 0; i0 < 256; i0 += 4) {
        ulonglong2 w0 = wp[(size_t)(i0 + 0) * 256];
        ulonglong2 w1 = wp[(size_t)(i0 + 1) * 256];
        ulonglong2 w2 = wp[(size_t)(i0 + 2) * 256];
        ulonglong2 w3 = wp[(size_t)(i0 + 3) * 256];
        UP_FMA(w0, xb + (size_t)(i0 + 0) * RPAD);
        UP_FMA(w1, xb + (size_t)(i0 + 1) * RPAD);
        UP_FMA(w2, xb + (size_t)(i0 + 2) * RPAD);
        UP_FMA(w3, xb + (size_t)(i0 + 3) * RPAD);
    }

    int h0 = hc * 512 + g * 4;
    #pragma unroll
    for (int j = 0; j < 8; j++) {
        int t = th * 8 + j;
        if (t < nt) {
            float w = s_wt[t];
            float2 v0 = unpk(a0[j]);
            float2 v1 = unpk(a1[j]);
            float* yr = y + (size_t)s_tok[t] * H + h0;
            atomicAdd(yr,     w * v0.x);
            atomicAdd(yr + 1, w * v0.y);
            atomicAdd(yr + 2, w * v1.x);
            atomicAdd(yr + 3, w * v1.y);
        }
    }
}

// ============================================================
extern "C" void kernel_launch(void* const* d_in, const int* in_sizes, int n_in,
                              void* d_out, int out_size)
{
    const float* x   = (const float*)d_in[0];
    const float* gw  = (const float*)d_in[1];
    const float* eb  = (const float*)d_in[2];
    const float* wg  = (const float*)d_in[3];
    const float* wu  = (const float*)d_in[4];
    const float* wd  = (const float*)d_in[5];
    const float* swg = (const float*)d_in[6];
    const float* swu = (const float*)d_in[7];
    const float* swd = (const float*)d_in[8];
    float* y = (float*)d_out;

    const int smem_bytes = 256 * RPAD * 8;   // 36864
    static int attr_done = 0;
    if (!attr_done) {
        cudaFuncSetAttribute(k_up,   cudaFuncAttributeMaxDynamicSharedMemorySize, smem_bytes);
        cudaFuncSetAttribute(k_down, cudaFuncAttributeMaxDynamicSharedMemorySize, smem_bytes);
        attr_done = 1;
    }

    k_init<<<256, 256>>>((float4*)y);
    k_route<<<64, 256>>>(x, gw, eb);
    k_scan<<<1, 256>>>();
    k_up<<<NSEG_MAX, 256, smem_bytes>>>(x, wg, wu, swg, swu);
    k_down<<<dim3(2, NSEG_MAX), 256, smem_bytes>>>(wd, swd, y);
}

// round 7
// speedup vs baseline: 1.1129x; 1.1129x over previous
#include <cuda_runtime.h>
#include <math.h>

#define T 256
#define H 1024
#define E 256
#define I_DIM 256
#define SEG_CAP 16
#define NSEG_MAX 416
#define NSLOT (2048 + 256)
#define NST 3
#define SROWS 8

typedef unsigned long long u64;

// ---- static scratch ----
__device__ int   d_cnt[E];
__device__ int   d_off[E];
__device__ int   d_tokbuf[E * T];
__device__ float d_wbuf[E * T];
__device__ int   d_nseg;
__device__ int   d_seg_e[NSEG_MAX];
__device__ int   d_seg_nt[NSEG_MAX];
__device__ int   d_seg_slot0[NSEG_MAX];
__device__ int   d_seg_tok[NSEG_MAX * SEG_CAP];
__device__ float d_seg_wt[NSEG_MAX * SEG_CAP];
__device__ __align__(16) float d_ps[NSLOT * I_DIM];

// ---- f32x2 helpers ----
__device__ __forceinline__ u64 dup2f(float v) {
    u64 r; asm("mov.b64 %0,{%1,%1};" : "=l"(r) : "f"(v)); return r;
}
__device__ __forceinline__ u64 fma2(u64 a, u64 b, u64 c) {
    u64 d; asm("fma.rn.f32x2 %0,%1,%2,%3;" : "=l"(d) : "l"(a), "l"(b), "l"(c)); return d;
}
__device__ __forceinline__ float2 unpk(u64 a) {
    float2 f; asm("mov.b64 {%0,%1},%2;" : "=f"(f.x), "=f"(f.y) : "l"(a)); return f;
}

// ---- mbarrier / bulk-copy helpers ----
__device__ __forceinline__ unsigned smem_u32(const void* p) {
    unsigned a;
    asm("{ .reg .u64 t; cvta.to.shared.u64 t, %1; cvt.u32.u64 %0, t; }" : "=r"(a) : "l"(p));
    return a;
}
__device__ __forceinline__ void mbar_init(unsigned a, unsigned cnt) {
    asm volatile("mbarrier.init.shared.b64 [%0], %1;" :: "r"(a), "r"(cnt) : "memory");
}
__device__ __forceinline__ void mbar_expect(unsigned a, unsigned bytes) {
    asm volatile("mbarrier.arrive.expect_tx.shared.b64 _, [%0], %1;" :: "r"(a), "r"(bytes) : "memory");
}
__device__ __forceinline__ void mbar_arrive(unsigned a) {
    asm volatile("mbarrier.arrive.shared.b64 _, [%0];" :: "r"(a) : "memory");
}
__device__ __forceinline__ void mbar_wait(unsigned a, unsigned ph) {
    unsigned done;
    asm volatile(
        "{\n\t.reg .pred p;\n\t"
        "mbarrier.try_wait.parity.acquire.cta.shared::cta.b64 p, [%1], %2;\n\t"
        "selp.b32 %0, 1, 0, p;\n\t}"
        : "=r"(done) : "r"(a), "r"(ph) : "memory");
    if (!done) {
        asm volatile(
            "{\n\t.reg .pred P1;\n\t"
            "W%=:\n\t"
            "mbarrier.try_wait.parity.acquire.cta.shared::cta.b64 P1, [%0], %1, 0x989680;\n\t"
            "@P1 bra.uni D%=;\n\t"
            "bra.uni W%=;\n\t"
            "D%=:\n\t}"
            :: "r"(a), "r"(ph) : "memory");
    }
}
__device__ __forceinline__ void bulk_g2s(unsigned dst, const void* src,
                                         unsigned bytes, unsigned mbar) {
    asm volatile(
        "cp.async.bulk.shared::cta.global.mbarrier::complete_tx::bytes [%0], [%1], %2, [%3];"
        :: "r"(dst), "l"(src), "r"(bytes), "r"(mbar) : "memory");
}

// ============================================================
// 0) init: zero output + per-expert counters
// ============================================================
__global__ void k_init(float4* y)
{
    y[blockIdx.x * 256 + threadIdx.x] = make_float4(0.f, 0.f, 0.f, 0.f);
    if (blockIdx.x == 0) d_cnt[threadIdx.x] = 0;
}

// ============================================================
// 1) gate logits + noaux_tc routing. 4 tokens per block.
// ============================================================
__global__ void k_route(const float* __restrict__ x,
                        const float* __restrict__ gw,
                        const float* __restrict__ ebias)
{
    __shared__ float xs[4][H];
    __shared__ float s_scores[4][E];
    __shared__ float s_sc[4][E];

    int tid  = threadIdx.x;
    int lane = tid & 31;
    int wid  = tid >> 5;
    int t0   = blockIdx.x * 4;

    for (int t = 0; t < 4; t++)
        for (int k = tid; k < H; k += 256)
            xs[t][k] = x[(t0 + t) * H + k];
    __syncthreads();

    for (int eo = 0; eo < 32; eo++) {
        int e = wid * 32 + eo;
        const float* wr = gw + e * H;
        float a0 = 0.f, a1 = 0.f, a2 = 0.f, a3 = 0.f;
        #pragma unroll 4
        for (int k = 0; k < 32; k++) {
            float wv = wr[k * 32 + lane];
            a0 += wv * xs[0][k * 32 + lane];
            a1 += wv * xs[1][k * 32 + lane];
            a2 += wv * xs[2][k * 32 + lane];
            a3 += wv * xs[3][k * 32 + lane];
        }
        for (int off = 16; off; off >>= 1) {
            a0 += __shfl_xor_sync(~0u, a0, off);
            a1 += __shfl_xor_sync(~0u, a1, off);
            a2 += __shfl_xor_sync(~0u, a2, off);
            a3 += __shfl_xor_sync(~0u, a3, off);
        }
        if (lane == 0) {
            float b = ebias[e];
            float s;
            s = 1.f / (1.f + expf(-a0)); s_scores[0][e] = s; s_sc[0][e] = s + b;
            s = 1.f / (1.f + expf(-a1)); s_scores[1][e] = s; s_sc[1][e] = s + b;
            s = 1.f / (1.f + expf(-a2)); s_scores[2][e] = s; s_sc[2][e] = s + b;
            s = 1.f / (1.f + expf(-a3)); s_scores[3][e] = s; s_sc[3][e] = s + b;
        }
    }
    __syncthreads();

    if (wid < 4) {
        int t     = wid;
        int tglob = t0 + t;

        float gs[8];
        #pragma unroll
        for (int g = 0; g < 8; g++) {
            float v  = s_sc[t][g * 32 + lane];
            float m1 = v; int i1 = lane;
            for (int off = 16; off; off >>= 1) {
                float ov = __shfl_xor_sync(~0u, m1, off);
                int   oi = __shfl_xor_sync(~0u, i1, off);
                if (ov > m1 || (ov == m1 && oi < i1)) { m1 = ov; i1 = oi; }
            }
            float v2 = (lane == i1) ? -INFINITY : v;
            for (int off = 16; off; off >>= 1)
                v2 = fmaxf(v2, __shfl_xor_sync(~0u, v2, off));
            gs[g] = m1 + v2;
        }

        unsigned gmask = 0;
        #pragma unroll
        for (int r = 0; r < 4; r++) {
            float bv = -INFINITY; int bg = 0;
            #pragma unroll
            for (int g = 0; g < 8; g++)
                if (!((gmask >> g) & 1) && gs[g] > bv) { bv = gs[g]; bg = g; }
            gmask |= 1u << bg;
        }

        float mv[8];
        #pragma unroll
        for (int j = 0; j < 8; j++)
            mv[j] = ((gmask >> j) & 1) ? s_sc[t][lane + 32 * j] : -INFINITY;

        int sel[8];
        #pragma unroll
        for (int r = 0; r < 8; r++) {
            float bv = -INFINITY; int be = 1 << 30;
            #pragma unroll
            for (int j = 0; j < 8; j++) {
                int e = lane + 32 * j;
                if (mv[j] > bv || (mv[j] == bv && e < be)) { bv = mv[j]; be = e; }
            }
            for (int off = 16; off; off >>= 1) {
                float ov = __shfl_xor_sync(~0u, bv, off);
                int   oe = __shfl_xor_sync(~0u, be, off);
                if (ov > bv || (ov == bv && oe < be)) { bv = ov; be = oe; }
            }
            sel[r] = be;
            if ((be & 31) == lane) mv[be >> 5] = -INFINITY;
        }

        float myv = (lane < 8) ? s_scores[t][sel[lane]] : 0.f;
        float sum = myv;
        for (int off = 16; off; off >>= 1)
            sum += __shfl_xor_sync(~0u, sum, off);
        if (lane < 8) {
            float wt = myv / (sum + 1e-20f) * 2.5f;
            int e = sel[lane];
            int pos = atomicAdd(&d_cnt[e], 1);
            d_tokbuf[e * T + pos] = tglob;
            d_wbuf[e * T + pos]  = wt;
        }
    }
}

// ============================================================
// 2) scan: per-expert offsets + segment list (+16 shared segs)
// ============================================================
__global__ void k_scan()
{
    __shared__ int s1[E], s2[E];
    int e = threadIdx.x;
    int n = d_cnt[e];

    s1[e] = n; __syncthreads();
    for (int d = 1; d < E; d <<= 1) {
        int v = (e >= d) ? s1[e - d] : 0;
        __syncthreads();
        s1[e] += v;
        __syncthreads();
    }
    int off = s1[e] - n;
    d_off[e] = off;

    int nseg = (n + SEG_CAP - 1) / SEG_CAP;
    s2[e] = nseg; __syncthreads();
    for (int d = 1; d < E; d <<= 1) {
        int v = (e >= d) ? s2[e - d] : 0;
        __syncthreads();
        s2[e] += v;
        __syncthreads();
    }
    int segbase = 16 + (s2[e] - nseg);
    if (e == E - 1) d_nseg = 16 + s2[E - 1];

    for (int si = 0; si < nseg; si++) {
        int sidx = segbase + si;
        int st   = si * SEG_CAP;
        int cnt  = min(SEG_CAP, n - st);
        d_seg_e[sidx]     = e;
        d_seg_nt[sidx]    = cnt;
        d_seg_slot0[sidx] = off + st;
        for (int j = 0; j < cnt; j++) {
            d_seg_tok[sidx * SEG_CAP + j] = d_tokbuf[e * T + st + j];
            d_seg_wt[sidx * SEG_CAP + j]  = d_wbuf[e * T + st + j];
        }
    }

    if (e < 16) {
        d_seg_e[e]     = E;
        d_seg_nt[e]    = SEG_CAP;
        d_seg_slot0[e] = 2048 + e * SEG_CAP;
        for (int j = 0; j < SEG_CAP; j++) {
            d_seg_tok[e * SEG_CAP + j] = e * SEG_CAP + j;
            d_seg_wt[e * SEG_CAP + j]  = 1.0f;
        }
    }
}

// ============================================================
// 3) up/gate with cp.async.bulk pipeline.
//    dsm layout (u64): [0,4096) x-dup quarter [hh*16+j];
//                      [4096, 4096+3*2048) weight stages
//    stage = 8 k-rows: gate 8KB @ +0, up 8KB @ +1024 u64.
//    thread: cp = tid&127 (2 cols), m = tid>>7 (gate/up).
// ============================================================
template <int NT>
__device__ __forceinline__ void up_pipe(
    const float* __restrict__ x, const char* __restrict__ wgp,
    const char* __restrict__ wup, float* __restrict__ psout, int nt,
    u64* dsm, const int* s_tok, unsigned mb_full, unsigned mb_empty, int tid)
{
    int cp = tid & 127;
    int m  = tid >> 7;
    u64 acc[NT];
    #pragma unroll
    for (int j = 0; j < NT; j++) acc[j] = 0ull;

    // prologue: fill all stages
    if (tid == 0) {
        #pragma unroll
        for (int s = 0; s < NST; s++) {
            mbar_expect(mb_full + 8 * s, 16384);
            bulk_g2s(smem_u32(dsm + 4096 + s * 2048),        wgp + (size_t)s * 8192, 8192, mb_full + 8 * s);
            bulk_g2s(smem_u32(dsm + 4096 + s * 2048 + 1024), wup + (size_t)s * 8192, 8192, mb_full + 8 * s);
        }
    }

    for (int it = 0; it < 128; it++) {
        if ((it & 31) == 0) {                 // restage x quarter
            __syncthreads();
            int q = it >> 5;
            for (int idx = tid; idx < 4096; idx += 256) {
                int hh = idx >> 4, j = idx & 15;
                dsm[idx] = dup2f(x[(size_t)s_tok[j] * H + q * 256 + hh]);
            }
            __syncthreads();
        }
        int slot    = it - (it / 3) * 3;
        unsigned ph = (unsigned)((it / 3) & 1);
        mbar_wait(mb_full + 8 * slot, ph);

        const u64* wst = dsm + 4096 + slot * 2048 + m * 1024 + cp;
        int kq = (it * 8) & 255;
        #pragma unroll
        for (int r = 0; r < SROWS; r++) {
            u64 w = wst[r * 128];
            const u64* xr = dsm + (size_t)(kq + r) * 16;
            #pragma unroll
            for (int p = 0; p < NT / 2; p++) {
                ulonglong2 xp = *(const ulonglong2*)(xr + 2 * p);
                acc[2 * p]     = fma2(xp.x, w, acc[2 * p]);
                acc[2 * p + 1] = fma2(xp.y, w, acc[2 * p + 1]);
            }
        }
        mbar_arrive(mb_empty + 8 * slot);
        if (tid == 0 && it + NST < 128) {
            mbar_wait(mb_empty + 8 * slot, ph);
            mbar_expect(mb_full + 8 * slot, 16384);
            bulk_g2s(smem_u32(dsm + 4096 + slot * 2048),        wgp + (size_t)(it + NST) * 8192, 8192, mb_full + 8 * slot);
            bulk_g2s(smem_u32(dsm + 4096 + slot * 2048 + 1024), wup + (size_t)(it + NST) * 8192, 8192, mb_full + 8 * slot);
        }
    }

    // epilogue: exchange gate partials via smem (reuse x area), combine
    __syncthreads();
    if (m == 0) {
        #pragma unroll
        for (int j = 0; j < NT; j++)
            dsm[(size_t)j * 128 + cp] = acc[j];
    }
    __syncthreads();
    if (m == 1) {
        #pragma unroll
        for (int j = 0; j < NT; j++) {
            if (j < nt) {
                float2 g = unpk(dsm[(size_t)j * 128 + cp]);
                float2 u = unpk(acc[j]);
                float2 r;
                r.x = g.x / (1.f + expf(-g.x)) * u.x;
                r.y = g.y / (1.f + expf(-g.y)) * u.y;
                *(float2*)(psout + (size_t)j * I_DIM + 2 * cp) = r;
            }
        }
    }
}

__global__ void __launch_bounds__(256, 2) k_up(
    const float* __restrict__ x,
    const float* __restrict__ w_gate, const float* __restrict__ w_up,
    const float* __restrict__ sw_gate, const float* __restrict__ sw_up)
{
    extern __shared__ u64 dsm[];                 // 81920 B
    __shared__ int s_tok[SEG_CAP];
    __shared__ __align__(8) u64 mbars[2 * NST];
    int seg = blockIdx.x;
    if (seg >= d_nseg) return;
    int e     = d_seg_e[seg];
    int nt    = d_seg_nt[seg];
    int slot0 = d_seg_slot0[seg];
    int tid   = threadIdx.x;

    if (tid < SEG_CAP) s_tok[tid] = d_seg_tok[seg * SEG_CAP + min(tid, nt - 1)];

    unsigned mb = smem_u32(mbars);
    if (tid == 0) {
        #pragma unroll
        for (int s = 0; s < NST; s++) {
            mbar_init(mb + 8 * s, 1);                  // full: tx-based
            mbar_init(mb + 8 * (NST + s), 256);        // empty: all threads
        }
    }
    __syncthreads();

    const char *wgp, *wup;
    if (e < E) {
        wgp = (const char*)(w_gate + (size_t)e * H * I_DIM);
        wup = (const char*)(w_up   + (size_t)e * H * I_DIM);
    } else {
        wgp = (const char*)sw_gate;
        wup = (const char*)sw_up;
    }
    float* psout = d_ps + (size_t)slot0 * I_DIM;

    if (nt <= 8) up_pipe<8>(x, wgp, wup, psout, nt, dsm, s_tok, mb, mb + 8 * NST, tid);
    else         up_pipe<16>(x, wgp, wup, psout, nt, dsm, s_tok, mb, mb + 8 * NST, tid);
}

// ============================================================
// 4) down projection with cp.async.bulk pipeline.
//    grid (2, seg): block covers 512 h-cols (hc half).
//    dsm: [0,4096) ps-dup [ii*16+j]; [4096,+3*2048) stages
//    stage = 8 i-rows x 2KB (8 bulk copies, row stride 4KB).
// ============================================================
template <int NT>
__device__ __forceinline__ void down_pipe(
    const char* __restrict__ wsrc, const float* __restrict__ psin,
    float* __restrict__ y, int nt, int hc,
    u64* dsm, const int* s_tok, const float* s_wt,
    unsigned mb_full, unsigned mb_empty, int tid)
{
    int cp = tid;                        // 0..255 col-pairs of the half
    u64 acc[NT];
    #pragma unroll
    for (int j = 0; j < NT; j++) acc[j] = 0ull;

    // stage ps-dup once
    for (int idx = tid; idx < 4096; idx += 256) {
        int ii = idx >> 4, j = idx & 15;
        dsm[idx] = dup2f(psin[(size_t)j * I_DIM + ii]);
    }

    if (tid == 0) {
        #pragma unroll
        for (int s = 0; s < NST; s++) {
            mbar_expect(mb_full + 8 * s, 16384);
            #pragma unroll
            for (int r = 0; r < SROWS; r++)
                bulk_g2s(smem_u32(dsm + 4096 + s * 2048 + r * 256),
                         wsrc + (size_t)(s * SROWS + r) * 4096, 2048, mb_full + 8 * s);
        }
    }
    __syncthreads();   // ps-dup visible to all

    for (int it = 0; it < 32; it++) {
        int slot    = it - (it / 3) * 3;
        unsigned ph = (unsigned)((it / 3) & 1);
        mbar_wait(mb_full + 8 * slot, ph);

        const u64* wst = dsm + 4096 + slot * 2048 + cp;
        #pragma unroll
        for (int r = 0; r < SROWS; r++) {
            u64 w = wst[r * 256];
            const u64* pr = dsm + (size_t)(it * 8 + r) * 16;
            #pragma unroll
            for (int p = 0; p < NT / 2; p++) {
                ulonglong2 xp = *(const ulonglong2*)(pr + 2 * p);
                acc[2 * p]     = fma2(xp.x, w, acc[2 * p]);
                acc[2 * p + 1] = fma2(xp.y, w, acc[2 * p + 1]);
            }
        }
        mbar_arrive(mb_empty + 8 * slot);
        if (tid == 0 && it + NST < 32) {
            mbar_wait(mb_empty + 8 * slot, ph);
            mbar_expect(mb_full + 8 * slot, 16384);
            #pragma unroll
            for (int r = 0; r < SROWS; r++)
                bulk_g2s(smem_u32(dsm + 4096 + slot * 2048 + r * 256),
                         wsrc + (size_t)((it + NST) * SROWS + r) * 4096, 2048, mb_full + 8 * slot);
        }
    }

    int h0 = hc * 512 + 2 * cp;
    #pragma unroll
    for (int j = 0; j < NT; j++) {
        if (j < nt) {
            float2 v = unpk(acc[j]);
            float w  = s_wt[j];
            float* yr = y + (size_t)s_tok[j] * H + h0;
            atomicAdd(yr,     w * v.x);
            atomicAdd(yr + 1, w * v.y);
        }
    }
}

__global__ void __launch_bounds__(256, 2) k_down(
    const float* __restrict__ w_down, const float* __restrict__ sw_down,
    float* __restrict__ y)
{
    extern __shared__ u64 dsm[];                 // 81920 B
    __shared__ int   s_tok[SEG_CAP];
    __shared__ float s_wt[SEG_CAP];
    __shared__ __align__(8) u64 mbars[2 * NST];
    int seg = blockIdx.y;
    if (seg >= d_nseg) return;
    int e     = d_seg_e[seg];
    int nt    = d_seg_nt[seg];
    int slot0 = d_seg_slot0[seg];
    int hc    = blockIdx.x;
    int tid   = threadIdx.x;

    if (tid < SEG_CAP) {
        s_tok[tid] = d_seg_tok[seg * SEG_CAP + min(tid, nt - 1)];
        s_wt[tid]  = (tid < nt) ? d_seg_wt[seg * SEG_CAP + tid] : 0.f;
    }
    unsigned mb = smem_u32(mbars);
    if (tid == 0) {
        #pragma unroll
        for (int s = 0; s < NST; s++) {
            mbar_init(mb + 8 * s, 1);
            mbar_init(mb + 8 * (NST + s), 256);
        }
    }
    __syncthreads();

    const char* wsrc = (const char*)((e < E) ? (w_down + (size_t)e * I_DIM * H) : sw_down)
                       + (size_t)hc * 2048;
    const float* psin = d_ps + (size_t)slot0 * I_DIM;

    if (nt <= 8) down_pipe<8>(wsrc, psin, y, nt, hc, dsm, s_tok, s_wt, mb, mb + 8 * NST, tid);
    else         down_pipe<16>(wsrc, psin, y, nt, hc, dsm, s_tok, s_wt, mb, mb + 8 * NST, tid);
}

// ============================================================
extern "C" void kernel_launch(void* const* d_in, const int* in_sizes, int n_in,
                              void* d_out, int out_size)
{
    const float* x   = (const float*)d_in[0];
    const float* gw  = (const float*)d_in[1];
    const float* eb  = (const float*)d_in[2];
    const float* wg  = (const float*)d_in[3];
    const float* wu  = (const float*)d_in[4];
    const float* wd  = (const float*)d_in[5];
    const float* swg = (const float*)d_in[6];
    const float* swu = (const float*)d_in[7];
    const float* swd = (const float*)d_in[8];
    float* y = (float*)d_out;

    const int smem_bytes = (4096 + NST * 2048) * 8;   // 81920
    static int attr_done = 0;
    if (!attr_done) {
        cudaFuncSetAttribute(k_up,   cudaFuncAttributeMaxDynamicSharedMemorySize, smem_bytes);
        cudaFuncSetAttribute(k_down, cudaFuncAttributeMaxDynamicSharedMemorySize, smem_bytes);
        attr_done = 1;
    }

    k_init<<<256, 256>>>((float4*)y);
    k_route<<<64, 256>>>(x, gw, eb);
    k_scan<<<1, 256>>>();
    k_up<<<NSEG_MAX, 256, smem_bytes>>>(x, wg, wu, swg, swu);
    k_down<<<dim3(2, NSEG_MAX), 256, smem_bytes>>>(wd, swd, y);
}